// round 1
// baseline (speedup 1.0000x reference)
#include <cuda_runtime.h>
#include <math.h>

// ---------------------------------------------------------------------------
// EncoderAttention3: fused 3-layer MLP over (B=16384) x (7 neighbors)
//   x[b,n] (73) -> tanh(LN(x W1 + b1)) (256) -> elu(h W2 + b2) (256)
//   latent[b] = (sum_n h2[b,n]) W3 + b3   (uses linearity of layer 3)
//   out[b] = concat(obs_ego[b] (48), latent[b] (64))
// ---------------------------------------------------------------------------

namespace {
constexpr int BATCHES = 16384;
constexpr int OBS_DIM = 216;
constexpr int EGO     = 48;
constexpr int NEIGH   = 7;
constexpr int DIN     = 73;    // 48 ego + 24 ado + 1 team id
constexpr int H       = 256;
constexpr int DOUT    = 64;
constexpr int OUT_DIM = 112;   // 48 + 64

constexpr int BPB     = 8;            // batches per block
constexpr int ROWS    = BPB * NEIGH;  // 56
constexpr int THREADS = 256;          // 8 warps; warp w = batch w of this block
constexpr int KT      = 64;           // W2 k-tile rows

// shared memory layout (in floats)
constexpr int XS_STRIDE = 76;                       // padded 73
constexpr int XS_OFF    = 0;
constexpr int XS_SZ     = ROWS * XS_STRIDE;         // 4256
constexpr int WB_OFF    = XS_OFF + XS_SZ;           // weight staging buffer
constexpr int WB_SZ     = DIN * H;                  // 18688 >= max(W1, W2 tile 16384, W3 16384)
constexpr int H1_OFF    = WB_OFF + WB_SZ;           // 22944
constexpr int H1_SZ     = ROWS * H;                 // 14336
constexpr int SS_OFF    = H1_OFF + H1_SZ;           // 37280
constexpr int SS_SZ     = BPB * H;                  // 2048
constexpr int SMEM_FLOATS = SS_OFF + SS_SZ;         // 39328
constexpr int SMEM_BYTES  = SMEM_FLOATS * 4;        // 157312
}  // namespace

__global__ void __launch_bounds__(THREADS, 1)
enc3_kernel(const float* __restrict__ obs,
            const float* __restrict__ W1, const float* __restrict__ b1,
            const float* __restrict__ ln_g, const float* __restrict__ ln_b,
            const float* __restrict__ W2, const float* __restrict__ b2,
            const float* __restrict__ W3, const float* __restrict__ b3,
            float* __restrict__ out)
{
    extern __shared__ float sm[];
    const int tid  = threadIdx.x;
    const int warp = tid >> 5;
    const int lane = tid & 31;
    const int b0   = blockIdx.x * BPB;

    // column ownership: lane owns cols [cA, cA+4) and [cB, cB+4)
    const int cA = lane * 4;
    const int cB = 128 + lane * 4;

    // ---- stage W1 into smem -------------------------------------------------
    {
        float*       dst = sm + WB_OFF;
        const float* src = W1;
        for (int i = tid; i < DIN * H; i += THREADS) dst[i] = src[i];
    }

    // ---- assemble x tiles (56 rows x 73) -----------------------------------
    for (int i = tid; i < ROWS * DIN; i += THREADS) {
        const int r  = i / DIN;
        const int f  = i - r * DIN;
        const int bb = r / NEIGH;
        const int n  = r - bb * NEIGH;
        const float* ob = obs + (size_t)(b0 + bb) * OBS_DIM;
        float v;
        if (f < EGO)            v = ob[f];
        else if (f < EGO + 24)  v = ob[EGO + (f - EGO) * NEIGH + n];  // ado transpose
        else                    v = (n >= 3) ? 1.0f : 0.0f;           // TEAM_IDS[1:]
        sm[XS_OFF + r * XS_STRIDE + f] = v;
    }

    // ---- pass-through ego copy to output -----------------------------------
    for (int i = tid; i < BPB * EGO; i += THREADS) {
        const int bb = i / EGO;
        const int f  = i - bb * EGO;
        out[(size_t)(b0 + bb) * OUT_DIM + f] = obs[(size_t)(b0 + bb) * OBS_DIM + f];
    }
    __syncthreads();

    // ---- GEMM1: [7 x 73] @ [73 x 256] per warp ------------------------------
    float acc[NEIGH][8];
#pragma unroll
    for (int r = 0; r < NEIGH; ++r)
#pragma unroll
        for (int j = 0; j < 8; ++j) acc[r][j] = 0.0f;

    {
        const float* xw = sm + XS_OFF + warp * NEIGH * XS_STRIDE;
        const float* wb = sm + WB_OFF;
        for (int f = 0; f < DIN; ++f) {
            const float4 wA = *reinterpret_cast<const float4*>(wb + f * H + cA);
            const float4 wB = *reinterpret_cast<const float4*>(wb + f * H + cB);
#pragma unroll
            for (int r = 0; r < NEIGH; ++r) {
                const float xv = xw[r * XS_STRIDE + f];
                acc[r][0] = fmaf(xv, wA.x, acc[r][0]);
                acc[r][1] = fmaf(xv, wA.y, acc[r][1]);
                acc[r][2] = fmaf(xv, wA.z, acc[r][2]);
                acc[r][3] = fmaf(xv, wA.w, acc[r][3]);
                acc[r][4] = fmaf(xv, wB.x, acc[r][4]);
                acc[r][5] = fmaf(xv, wB.y, acc[r][5]);
                acc[r][6] = fmaf(xv, wB.z, acc[r][6]);
                acc[r][7] = fmaf(xv, wB.w, acc[r][7]);
            }
        }
    }

    // ---- bias + LayerNorm + tanh -> h1 (smem) -------------------------------
    {
        const float4 b1A = *reinterpret_cast<const float4*>(b1 + cA);
        const float4 b1B = *reinterpret_cast<const float4*>(b1 + cB);
        const float4 gA  = *reinterpret_cast<const float4*>(ln_g + cA);
        const float4 gB  = *reinterpret_cast<const float4*>(ln_g + cB);
        const float4 bA  = *reinterpret_cast<const float4*>(ln_b + cA);
        const float4 bB  = *reinterpret_cast<const float4*>(ln_b + cB);
        const float bia[8] = {b1A.x, b1A.y, b1A.z, b1A.w, b1B.x, b1B.y, b1B.z, b1B.w};
        const float gg[8]  = {gA.x, gA.y, gA.z, gA.w, gB.x, gB.y, gB.z, gB.w};
        const float bb_[8] = {bA.x, bA.y, bA.z, bA.w, bB.x, bB.y, bB.z, bB.w};

        float* h1w = sm + H1_OFF + warp * NEIGH * H;
#pragma unroll
        for (int r = 0; r < NEIGH; ++r) {
            float s = 0.0f, s2 = 0.0f;
#pragma unroll
            for (int j = 0; j < 8; ++j) {
                const float v = acc[r][j] + bia[j];
                acc[r][j] = v;
                s  += v;
                s2 = fmaf(v, v, s2);
            }
#pragma unroll
            for (int o = 16; o > 0; o >>= 1) {
                s  += __shfl_xor_sync(0xffffffffu, s,  o);
                s2 += __shfl_xor_sync(0xffffffffu, s2, o);
            }
            const float mu   = s * (1.0f / 256.0f);
            const float var  = fmaf(s2, 1.0f / 256.0f, -mu * mu);
            const float rstd = rsqrtf(var + 1e-5f);
            float v[8];
#pragma unroll
            for (int j = 0; j < 8; ++j)
                v[j] = tanhf(fmaf((acc[r][j] - mu) * rstd, gg[j], bb_[j]));
            *reinterpret_cast<float4*>(h1w + r * H + cA) = make_float4(v[0], v[1], v[2], v[3]);
            *reinterpret_cast<float4*>(h1w + r * H + cB) = make_float4(v[4], v[5], v[6], v[7]);
        }
    }

    // ---- GEMM2: [7 x 256] @ [256 x 256] per warp, W2 k-tiled through smem ---
#pragma unroll
    for (int r = 0; r < NEIGH; ++r)
#pragma unroll
        for (int j = 0; j < 8; ++j) acc[r][j] = 0.0f;

    {
        const float* h1w = sm + H1_OFF + warp * NEIGH * H;
        for (int kt = 0; kt < H / KT; ++kt) {
            __syncthreads();  // protects wbuf (still W1 on first pass / prev tile)
            {
                const float4* src = reinterpret_cast<const float4*>(W2 + (size_t)kt * KT * H);
                float4*       dst = reinterpret_cast<float4*>(sm + WB_OFF);
#pragma unroll
                for (int i = 0; i < (KT * H / 4) / THREADS; ++i)
                    dst[tid + i * THREADS] = src[tid + i * THREADS];
            }
            __syncthreads();
            const float* hk = h1w + kt * KT;
            const float* wb = sm + WB_OFF;
#pragma unroll 2
            for (int k = 0; k < KT; ++k) {
                const float4 wA = *reinterpret_cast<const float4*>(wb + k * H + cA);
                const float4 wB = *reinterpret_cast<const float4*>(wb + k * H + cB);
#pragma unroll
                for (int r = 0; r < NEIGH; ++r) {
                    const float xv = hk[r * H + k];
                    acc[r][0] = fmaf(xv, wA.x, acc[r][0]);
                    acc[r][1] = fmaf(xv, wA.y, acc[r][1]);
                    acc[r][2] = fmaf(xv, wA.z, acc[r][2]);
                    acc[r][3] = fmaf(xv, wA.w, acc[r][3]);
                    acc[r][4] = fmaf(xv, wB.x, acc[r][4]);
                    acc[r][5] = fmaf(xv, wB.y, acc[r][5]);
                    acc[r][6] = fmaf(xv, wB.z, acc[r][6]);
                    acc[r][7] = fmaf(xv, wB.w, acc[r][7]);
                }
            }
        }
    }

    // ---- bias + ELU, then sum over neighbors -> ss (smem) -------------------
    {
        const float4 b2A = *reinterpret_cast<const float4*>(b2 + cA);
        const float4 b2B = *reinterpret_cast<const float4*>(b2 + cB);
        const float bia[8] = {b2A.x, b2A.y, b2A.z, b2A.w, b2B.x, b2B.y, b2B.z, b2B.w};
        float sl[8];
#pragma unroll
        for (int j = 0; j < 8; ++j) sl[j] = 0.0f;
#pragma unroll
        for (int r = 0; r < NEIGH; ++r) {
#pragma unroll
            for (int j = 0; j < 8; ++j) {
                float v = acc[r][j] + bia[j];
                v = (v > 0.0f) ? v : expm1f(v);
                sl[j] += v;
            }
        }
        float* ssw = sm + SS_OFF + warp * H;
        *reinterpret_cast<float4*>(ssw + cA) = make_float4(sl[0], sl[1], sl[2], sl[3]);
        *reinterpret_cast<float4*>(ssw + cB) = make_float4(sl[4], sl[5], sl[6], sl[7]);
    }
    __syncthreads();

    // ---- stage W3 (256 x 64) into smem --------------------------------------
    {
        const float4* src = reinterpret_cast<const float4*>(W3);
        float4*       dst = reinterpret_cast<float4*>(sm + WB_OFF);
#pragma unroll
        for (int i = 0; i < (H * DOUT / 4) / THREADS; ++i)
            dst[tid + i * THREADS] = src[tid + i * THREADS];
    }
    __syncthreads();

    // ---- GEMM3: latent[b] = ss[b] @ W3 + b3 (per warp) ----------------------
    {
        const float* sw = sm + SS_OFF + warp * H;
        const float* w3 = sm + WB_OFF;
        float a0 = 0.0f, a1 = 0.0f;
#pragma unroll 4
        for (int k = 0; k < H; ++k) {
            const float sk = sw[k];
            a0 = fmaf(sk, w3[k * DOUT + lane],      a0);
            a1 = fmaf(sk, w3[k * DOUT + lane + 32], a1);
        }
        float* orow = out + (size_t)(b0 + warp) * OUT_DIM + EGO;
        orow[lane]      = a0 + b3[lane];
        orow[lane + 32] = a1 + b3[lane + 32];
    }
}

extern "C" void kernel_launch(void* const* d_in, const int* in_sizes, int n_in,
                              void* d_out, int out_size)
{
    (void)in_sizes; (void)n_in; (void)out_size;
    const float* obs  = (const float*)d_in[0];
    const float* W1   = (const float*)d_in[1];
    const float* b1   = (const float*)d_in[2];
    const float* ln_g = (const float*)d_in[3];
    const float* ln_b = (const float*)d_in[4];
    const float* W2   = (const float*)d_in[5];
    const float* b2   = (const float*)d_in[6];
    const float* W3   = (const float*)d_in[7];
    const float* b3   = (const float*)d_in[8];
    float* out = (float*)d_out;

    cudaFuncSetAttribute(enc3_kernel, cudaFuncAttributeMaxDynamicSharedMemorySize, SMEM_BYTES);
    enc3_kernel<<<BATCHES / BPB, THREADS, SMEM_BYTES>>>(
        obs, W1, b1, ln_g, ln_b, W2, b2, W3, b3, out);
}

// round 2
// speedup vs baseline: 1.2067x; 1.2067x over previous
#include <cuda_runtime.h>
#include <math.h>
#include <stdint.h>

// ---------------------------------------------------------------------------
// EncoderAttention3: fused 3-layer MLP over (B=16384) x (7 neighbors)
// R1: packed f32x2 FMA (Blackwell FFMA2) + cp.async double-buffered W2 tiles.
// ---------------------------------------------------------------------------

namespace {
constexpr int BATCHES = 16384;
constexpr int OBS_DIM = 216;
constexpr int EGO     = 48;
constexpr int NEIGH   = 7;
constexpr int DIN     = 73;
constexpr int H       = 256;
constexpr int DOUT    = 64;
constexpr int OUT_DIM = 112;

constexpr int BPB     = 8;
constexpr int ROWS    = BPB * NEIGH;   // 56
constexpr int THREADS = 256;
constexpr int KT      = 32;            // W2 k-tile rows
constexpr int NT      = H / KT;        // 8 tiles

// shared memory layout (floats)
constexpr int XS_STRIDE = 76;
constexpr int XS_OFF  = 0;
constexpr int XS_SZ   = ROWS * XS_STRIDE;        // 4256
constexpr int WA_OFF  = XS_OFF + XS_SZ;          // 4256   (W1 staging; dead after GEMM1)
constexpr int WA_SZ   = DIN * H;                 // 18688
constexpr int SS_OFF  = WA_OFF;                  // alias into dead W1 region
constexpr int W3_OFF  = WA_OFF + BPB * H;        // 6304   (W3 staging, also in dead W1)
constexpr int WB_OFF  = WA_OFF + WA_SZ;          // 22944  (W2 tile double buffer)
constexpr int WB_SZ   = 2 * KT * H;              // 16384
constexpr int H1_OFF  = WB_OFF + WB_SZ;          // 39328
constexpr int H1_SZ   = ROWS * H;                // 14336
constexpr int SMEM_FLOATS = H1_OFF + H1_SZ;      // 53664
constexpr int SMEM_BYTES  = SMEM_FLOATS * 4;     // 214656
}  // namespace

// ---- packed f32x2 helpers --------------------------------------------------
__device__ __forceinline__ unsigned long long bcast2(float x) {
    unsigned long long r;
    asm("mov.b64 %0, {%1, %1};" : "=l"(r) : "f"(x));
    return r;
}
__device__ __forceinline__ void fma2(unsigned long long& d,
                                     unsigned long long a, unsigned long long b) {
    asm("fma.rn.f32x2 %0, %1, %2, %0;" : "+l"(d) : "l"(a), "l"(b));
}
__device__ __forceinline__ float2 unpack2(unsigned long long v) {
    float2 f;
    asm("mov.b64 {%0, %1}, %2;" : "=f"(f.x), "=f"(f.y) : "l"(v));
    return f;
}

// ---- cp.async helpers -------------------------------------------------------
__device__ __forceinline__ void cp16(uint32_t dst_smem, const void* src) {
    asm volatile("cp.async.cg.shared.global [%0], [%1], 16;" :: "r"(dst_smem), "l"(src));
}
#define CP_COMMIT() asm volatile("cp.async.commit_group;" ::: "memory")
#define CP_WAIT(n)  asm volatile("cp.async.wait_group %0;" :: "n"(n) : "memory")

__global__ void __launch_bounds__(THREADS, 1)
enc3_kernel(const float* __restrict__ obs,
            const float* __restrict__ W1, const float* __restrict__ b1,
            const float* __restrict__ ln_g, const float* __restrict__ ln_b,
            const float* __restrict__ W2, const float* __restrict__ b2,
            const float* __restrict__ W3, const float* __restrict__ b3,
            float* __restrict__ out)
{
    extern __shared__ float sm[];
    const int tid  = threadIdx.x;
    const int warp = tid >> 5;
    const int lane = tid & 31;
    const int b0   = blockIdx.x * BPB;

    const uint32_t sm_u32 = (uint32_t)__cvta_generic_to_shared(sm);

    // lane owns cols [cA,cA+4) and [cB,cB+4)
    const int cA = lane * 4;
    const int cB = 128 + lane * 4;

    // ---- group0: W1 staging via cp.async -----------------------------------
    {
        const float4* src = reinterpret_cast<const float4*>(W1);
        const uint32_t dst = sm_u32 + WA_OFF * 4;
        for (int i = tid; i < DIN * H / 4; i += THREADS)
            cp16(dst + i * 16, src + i);
        CP_COMMIT();
    }
    // ---- group1: W2 tile 0 prefetch -----------------------------------------
    {
        const float4* src = reinterpret_cast<const float4*>(W2);
        const uint32_t dst = sm_u32 + WB_OFF * 4;
#pragma unroll
        for (int i = 0; i < (KT * H / 4) / THREADS; ++i)
            cp16(dst + (tid + i * THREADS) * 16, src + tid + i * THREADS);
        CP_COMMIT();
    }

    // ---- assemble x tiles (56 x 73) while copies fly ------------------------
    for (int i = tid; i < ROWS * DIN; i += THREADS) {
        const int r  = i / DIN;
        const int f  = i - r * DIN;
        const int bb = r / NEIGH;
        const int n  = r - bb * NEIGH;
        const float* ob = obs + (size_t)(b0 + bb) * OBS_DIM;
        float v;
        if (f < EGO)            v = ob[f];
        else if (f < EGO + 24)  v = ob[EGO + (f - EGO) * NEIGH + n];
        else                    v = (n >= 3) ? 1.0f : 0.0f;
        sm[XS_OFF + r * XS_STRIDE + f] = v;
    }
    // ego pass-through
    for (int i = tid; i < BPB * EGO; i += THREADS) {
        const int bb = i / EGO;
        const int f  = i - bb * EGO;
        out[(size_t)(b0 + bb) * OUT_DIM + f] = obs[(size_t)(b0 + bb) * OBS_DIM + f];
    }

    CP_WAIT(1);          // W1 landed (tile0 may still be pending)
    __syncthreads();

    // ---- GEMM1: [7 x 73] @ [73 x 256] per warp, packed f32x2 ----------------
    unsigned long long acc[NEIGH][4];
#pragma unroll
    for (int r = 0; r < NEIGH; ++r)
#pragma unroll
        for (int j = 0; j < 4; ++j) acc[r][j] = 0ull;

    {
        const float* xw = sm + XS_OFF + warp * NEIGH * XS_STRIDE;
        const float* wb = sm + WA_OFF;
#pragma unroll 2
        for (int f4 = 0; f4 < DIN / 4; ++f4) {           // 18 blocks of 4
            float4 xq[NEIGH];
#pragma unroll
            for (int r = 0; r < NEIGH; ++r)
                xq[r] = *reinterpret_cast<const float4*>(xw + r * XS_STRIDE + f4 * 4);
#pragma unroll
            for (int kk = 0; kk < 4; ++kk) {
                const int f = f4 * 4 + kk;
                const ulonglong2 wA = *reinterpret_cast<const ulonglong2*>(wb + f * H + cA);
                const ulonglong2 wB = *reinterpret_cast<const ulonglong2*>(wb + f * H + cB);
#pragma unroll
                for (int r = 0; r < NEIGH; ++r) {
                    const float xv = (kk == 0) ? xq[r].x : (kk == 1) ? xq[r].y
                                   : (kk == 2) ? xq[r].z : xq[r].w;
                    const unsigned long long xp = bcast2(xv);
                    fma2(acc[r][0], xp, wA.x);
                    fma2(acc[r][1], xp, wA.y);
                    fma2(acc[r][2], xp, wB.x);
                    fma2(acc[r][3], xp, wB.y);
                }
            }
        }
        // tail f = 72
        {
            const int f = 72;
            const ulonglong2 wA = *reinterpret_cast<const ulonglong2*>(wb + f * H + cA);
            const ulonglong2 wB = *reinterpret_cast<const ulonglong2*>(wb + f * H + cB);
#pragma unroll
            for (int r = 0; r < NEIGH; ++r) {
                const unsigned long long xp = bcast2(xw[r * XS_STRIDE + f]);
                fma2(acc[r][0], xp, wA.x);
                fma2(acc[r][1], xp, wA.y);
                fma2(acc[r][2], xp, wB.x);
                fma2(acc[r][3], xp, wB.y);
            }
        }
    }

    // ---- bias + LayerNorm + tanh -> h1 (smem, warp-private) -----------------
    {
        const float4 b1A = *reinterpret_cast<const float4*>(b1 + cA);
        const float4 b1B = *reinterpret_cast<const float4*>(b1 + cB);
        const float4 gA  = *reinterpret_cast<const float4*>(ln_g + cA);
        const float4 gB  = *reinterpret_cast<const float4*>(ln_g + cB);
        const float4 bA  = *reinterpret_cast<const float4*>(ln_b + cA);
        const float4 bB  = *reinterpret_cast<const float4*>(ln_b + cB);
        const float bia[8] = {b1A.x, b1A.y, b1A.z, b1A.w, b1B.x, b1B.y, b1B.z, b1B.w};
        const float gg[8]  = {gA.x, gA.y, gA.z, gA.w, gB.x, gB.y, gB.z, gB.w};
        const float bb_[8] = {bA.x, bA.y, bA.z, bA.w, bB.x, bB.y, bB.z, bB.w};

        float* h1w = sm + H1_OFF + warp * NEIGH * H;
#pragma unroll
        for (int r = 0; r < NEIGH; ++r) {
            float v[8];
            const float2 p0 = unpack2(acc[r][0]);
            const float2 p1 = unpack2(acc[r][1]);
            const float2 p2 = unpack2(acc[r][2]);
            const float2 p3 = unpack2(acc[r][3]);
            v[0] = p0.x; v[1] = p0.y; v[2] = p1.x; v[3] = p1.y;
            v[4] = p2.x; v[5] = p2.y; v[6] = p3.x; v[7] = p3.y;
            float s = 0.0f, s2 = 0.0f;
#pragma unroll
            for (int j = 0; j < 8; ++j) {
                v[j] += bia[j];
                s  += v[j];
                s2 = fmaf(v[j], v[j], s2);
            }
#pragma unroll
            for (int o = 16; o > 0; o >>= 1) {
                s  += __shfl_xor_sync(0xffffffffu, s,  o);
                s2 += __shfl_xor_sync(0xffffffffu, s2, o);
            }
            const float mu   = s * (1.0f / 256.0f);
            const float var  = fmaf(s2, 1.0f / 256.0f, -mu * mu);
            const float rstd = rsqrtf(var + 1e-5f);
#pragma unroll
            for (int j = 0; j < 8; ++j)
                v[j] = tanhf(fmaf((v[j] - mu) * rstd, gg[j], bb_[j]));
            *reinterpret_cast<float4*>(h1w + r * H + cA) = make_float4(v[0], v[1], v[2], v[3]);
            *reinterpret_cast<float4*>(h1w + r * H + cB) = make_float4(v[4], v[5], v[6], v[7]);
        }
    }

    // ---- GEMM2: [7 x 256] @ [256 x 256], cp.async double-buffered tiles -----
#pragma unroll
    for (int r = 0; r < NEIGH; ++r)
#pragma unroll
        for (int j = 0; j < 4; ++j) acc[r][j] = 0ull;

    {
        const float* h1w = sm + H1_OFF + warp * NEIGH * H;
        for (int kt = 0; kt < NT; ++kt) {
            // prefetch next tile (or W3 on the last iteration)
            if (kt + 1 < NT) {
                const float4* src = reinterpret_cast<const float4*>(W2 + (size_t)(kt + 1) * KT * H);
                const uint32_t dst = sm_u32 + (WB_OFF + ((kt + 1) & 1) * (KT * H)) * 4;
#pragma unroll
                for (int i = 0; i < (KT * H / 4) / THREADS; ++i)
                    cp16(dst + (tid + i * THREADS) * 16, src + tid + i * THREADS);
            } else {
                const float4* src = reinterpret_cast<const float4*>(W3);
                const uint32_t dst = sm_u32 + W3_OFF * 4;
#pragma unroll
                for (int i = 0; i < (H * DOUT / 4) / THREADS; ++i)
                    cp16(dst + (tid + i * THREADS) * 16, src + tid + i * THREADS);
            }
            CP_COMMIT();
            CP_WAIT(1);          // current tile kt resident
            __syncthreads();

            const float* hk = h1w + kt * KT;
            const float* wb = sm + WB_OFF + (kt & 1) * (KT * H);
#pragma unroll 2
            for (int k4 = 0; k4 < KT / 4; ++k4) {
                float4 xq[NEIGH];
#pragma unroll
                for (int r = 0; r < NEIGH; ++r)
                    xq[r] = *reinterpret_cast<const float4*>(hk + r * H + k4 * 4);
#pragma unroll
                for (int kk = 0; kk < 4; ++kk) {
                    const int k = k4 * 4 + kk;
                    const ulonglong2 wA = *reinterpret_cast<const ulonglong2*>(wb + k * H + cA);
                    const ulonglong2 wB = *reinterpret_cast<const ulonglong2*>(wb + k * H + cB);
#pragma unroll
                    for (int r = 0; r < NEIGH; ++r) {
                        const float xv = (kk == 0) ? xq[r].x : (kk == 1) ? xq[r].y
                                       : (kk == 2) ? xq[r].z : xq[r].w;
                        const unsigned long long xp = bcast2(xv);
                        fma2(acc[r][0], xp, wA.x);
                        fma2(acc[r][1], xp, wA.y);
                        fma2(acc[r][2], xp, wB.x);
                        fma2(acc[r][3], xp, wB.y);
                    }
                }
            }
            __syncthreads();     // everyone done with this buffer before overwrite
        }
    }

    // ---- bias + ELU, neighbor-sum -> ss (smem, warp-private region) ---------
    {
        const float4 b2A = *reinterpret_cast<const float4*>(b2 + cA);
        const float4 b2B = *reinterpret_cast<const float4*>(b2 + cB);
        const float bia[8] = {b2A.x, b2A.y, b2A.z, b2A.w, b2B.x, b2B.y, b2B.z, b2B.w};
        float sl[8];
#pragma unroll
        for (int j = 0; j < 8; ++j) sl[j] = 0.0f;
#pragma unroll
        for (int r = 0; r < NEIGH; ++r) {
            float v[8];
            const float2 p0 = unpack2(acc[r][0]);
            const float2 p1 = unpack2(acc[r][1]);
            const float2 p2 = unpack2(acc[r][2]);
            const float2 p3 = unpack2(acc[r][3]);
            v[0] = p0.x; v[1] = p0.y; v[2] = p1.x; v[3] = p1.y;
            v[4] = p2.x; v[5] = p2.y; v[6] = p3.x; v[7] = p3.y;
#pragma unroll
            for (int j = 0; j < 8; ++j) {
                float t = v[j] + bia[j];
                t = (t > 0.0f) ? t : expm1f(t);
                sl[j] += t;
            }
        }
        float* ssw = sm + SS_OFF + warp * H;
        *reinterpret_cast<float4*>(ssw + cA) = make_float4(sl[0], sl[1], sl[2], sl[3]);
        *reinterpret_cast<float4*>(ssw + cB) = make_float4(sl[4], sl[5], sl[6], sl[7]);
    }

    CP_WAIT(0);          // W3 resident
    __syncthreads();     // ss + W3 visible block-wide

    // ---- GEMM3: latent[b] = ss[b] @ W3 + b3 (per warp) ----------------------
    {
        const float* sw = sm + SS_OFF + warp * H;
        const float* w3 = sm + W3_OFF;
        float a0 = 0.0f, a1 = 0.0f;
#pragma unroll 4
        for (int k = 0; k < H; ++k) {
            const float sk = sw[k];
            a0 = fmaf(sk, w3[k * DOUT + lane],      a0);
            a1 = fmaf(sk, w3[k * DOUT + lane + 32], a1);
        }
        float* orow = out + (size_t)(b0 + warp) * OUT_DIM + EGO;
        orow[lane]      = a0 + b3[lane];
        orow[lane + 32] = a1 + b3[lane + 32];
    }
}

extern "C" void kernel_launch(void* const* d_in, const int* in_sizes, int n_in,
                              void* d_out, int out_size)
{
    (void)in_sizes; (void)n_in; (void)out_size;
    const float* obs  = (const float*)d_in[0];
    const float* W1   = (const float*)d_in[1];
    const float* b1   = (const float*)d_in[2];
    const float* ln_g = (const float*)d_in[3];
    const float* ln_b = (const float*)d_in[4];
    const float* W2   = (const float*)d_in[5];
    const float* b2   = (const float*)d_in[6];
    const float* W3   = (const float*)d_in[7];
    const float* b3   = (const float*)d_in[8];
    float* out = (float*)d_out;

    cudaFuncSetAttribute(enc3_kernel, cudaFuncAttributeMaxDynamicSharedMemorySize, SMEM_BYTES);
    enc3_kernel<<<BATCHES / BPB, THREADS, SMEM_BYTES>>>(
        obs, W1, b1, ln_g, ln_b, W2, b2, W3, b3, out);
}

// round 4
// speedup vs baseline: 1.9254x; 1.5956x over previous
#include <cuda_runtime.h>
#include <math.h>
#include <stdint.h>

// ===========================================================================
// EncoderAttention3 via mma.sync tf32 (m16n8k8), register accumulators.
//   Per CTA: 8 batches -> M=64 rows (56 valid), N=256.
//   GEMM1: X[64x96] @ W1 -> +b1, LayerNorm, tanh -> h1 (tf32, smem)
//   GEMM2: h1 @ W2 (8 K-chunks, cp.async double-buffered) -> +b2, ELU
//   neighbor-sum(7) -> ss[8x256];  GEMM3 (SIMT): ss @ W3 + b3
//   out = concat(ego, latent)
// ===========================================================================

namespace {
constexpr int OBS_DIM = 216, EGO = 48, NEIGH = 7, H = 256, DOUT = 64, OUT_DIM = 112;
constexpr int BATCHES = 16384;
constexpr int BPB     = 8;
constexpr int RVALID  = BPB * NEIGH;   // 56
constexpr int M       = 64;
constexpr int K1      = 96;            // padded 73 -> 96 (3 chunks of 32)
constexpr int THREADS = 256;
constexpr int NCHUNK  = 3 + 8;         // 3 W1 chunks + 8 W2 chunks
constexpr int WS      = 264;           // weight chunk row stride (floats)
constexpr int XS      = 100;           // X row stride
constexpr int H1S     = 260;           // h1 row stride

// smem layout (float offsets)
constexpr int B1C = 0;            // 256
constexpr int GC  = 256;          // 256
constexpr int BBC = 512;          // 256
constexpr int B2C = 768;          // 256
constexpr int B3C = 1024;         // 64
constexpr int PSU = 1088;         // [4][64] partial sums
constexpr int PSQ = 1344;         // [4][64] partial sumsq
constexpr int SSO = 1600;         // ss [8][256]
constexpr int XO  = 3712;         // X  [64][100]
constexpr int H1O = 10112;        // h1 [64][260]
constexpr int BUF = 26752;        // 2 x [32][264] weight chunk double buffer
constexpr int BUFSZ = 32 * WS;    // 8448
constexpr int SMEM_FLOATS = BUF + 2 * BUFSZ;   // 43648
constexpr int SMEM_BYTES  = SMEM_FLOATS * 4;   // 174592
}  // namespace

__device__ float g_w1[K1 * WS];       // tf32-rounded, padded [96][264]
__device__ float g_w2[H * WS];        // tf32-rounded, padded [256][264]

// ---------------------------------------------------------------------------
__device__ __forceinline__ uint32_t tf32r(float f) {
    uint32_t u;
    asm("cvt.rna.tf32.f32 %0, %1;" : "=r"(u) : "f"(f));
    return u;
}
__device__ __forceinline__ void cp16(uint32_t dst, const void* src) {
    asm volatile("cp.async.cg.shared.global [%0], [%1], 16;" :: "r"(dst), "l"(src));
}
#define CP_COMMIT() asm volatile("cp.async.commit_group;" ::: "memory")
#define CP_WAIT(n)  asm volatile("cp.async.wait_group %0;" :: "n"(n) : "memory")

__device__ __forceinline__ void mma8(float d[4], const uint32_t a[4],
                                     uint32_t b0, uint32_t b1) {
    asm volatile("mma.sync.aligned.m16n8k8.row.col.f32.tf32.tf32.f32 "
                 "{%0,%1,%2,%3},{%4,%5,%6,%7},{%8,%9},{%0,%1,%2,%3};"
                 : "+f"(d[0]), "+f"(d[1]), "+f"(d[2]), "+f"(d[3])
                 : "r"(a[0]), "r"(a[1]), "r"(a[2]), "r"(a[3]), "r"(b0), "r"(b1));
}

// one 32-k chunk of a GEMM: A[m64 x *] (smem, stride as), B chunk buf [32][WS]
__device__ __forceinline__ void gemm_chunk(const float* __restrict__ A, int as, int k0,
                                           const float* __restrict__ B,
                                           float d[2][8][4], int rb, int cb, int lane) {
    const int lq = lane >> 2, lr = lane & 3;
#pragma unroll
    for (int ks = 0; ks < 4; ++ks) {
        const int kk = ks * 8;
        uint32_t a[2][4];
#pragma unroll
        for (int t = 0; t < 2; ++t) {
            const float* ap = A + (rb + t * 16 + lq) * as + k0 + kk + lr;
            a[t][0] = __float_as_uint(ap[0]);
            a[t][1] = __float_as_uint(ap[8 * as]);
            a[t][2] = __float_as_uint(ap[4]);
            a[t][3] = __float_as_uint(ap[8 * as + 4]);
        }
#pragma unroll
        for (int j = 0; j < 8; ++j) {
            const float* bp = B + (kk + lr) * WS + cb + j * 8 + lq;
            const uint32_t b0 = __float_as_uint(bp[0]);
            const uint32_t b1 = __float_as_uint(bp[4 * WS]);
            mma8(d[0][j], a[0], b0, b1);
            mma8(d[1][j], a[1], b0, b1);
        }
    }
}

// ---------------------------------------------------------------------------
// prep: tf32-round + pad W1/W2 into chunk-friendly images
// ---------------------------------------------------------------------------
__global__ void prep_kernel(const float* __restrict__ W1, const float* __restrict__ W2) {
    const int idx = blockIdx.x * blockDim.x + threadIdx.x;
    if (idx < K1 * WS) {
        const int k = idx / WS, n = idx - k * WS;
        const float v = (k < 73 && n < H) ? W1[k * H + n] : 0.0f;
        g_w1[idx] = __uint_as_float(tf32r(v));
    } else if (idx < (K1 + H) * WS) {
        const int i2 = idx - K1 * WS;
        const int k = i2 / WS, n = i2 - k * WS;
        const float v = (n < H) ? W2[k * H + n] : 0.0f;
        g_w2[i2] = __uint_as_float(tf32r(v));
    }
}

// ---------------------------------------------------------------------------
__global__ void __launch_bounds__(THREADS, 1)
enc3_mma_kernel(const float* __restrict__ obs,
                const float* __restrict__ b1, const float* __restrict__ ln_g,
                const float* __restrict__ ln_b, const float* __restrict__ b2,
                const float* __restrict__ W3, const float* __restrict__ b3,
                float* __restrict__ out)
{
    extern __shared__ float sm[];
    const int tid  = threadIdx.x;
    const int wid  = tid >> 5;
    const int lane = tid & 31;
    const int lq   = lane >> 2, lr = lane & 3;
    const int wr   = wid >> 2;           // row group 0/1 (32 rows)
    const int wc   = wid & 3;            // col group (64 cols)
    const int rb   = wr * 32;
    const int cb   = wc * 64;
    const int b0   = blockIdx.x * BPB;
    const uint32_t smu = (uint32_t)__cvta_generic_to_shared(sm);

    // ---- chunk 0 (W1) + all const vectors : group 0 -------------------------
    {
        const float4* src = (const float4*)g_w1;
        const uint32_t dst = smu + BUF * 4;
        for (int i = tid; i < BUFSZ / 4; i += THREADS) cp16(dst + i * 16, src + i);
        if (tid < 64)       cp16(smu + B1C * 4 + tid * 16, (const float4*)b1 + tid);
        else if (tid < 128) cp16(smu + GC  * 4 + (tid - 64) * 16, (const float4*)ln_g + (tid - 64));
        else if (tid < 192) cp16(smu + BBC * 4 + (tid - 128) * 16, (const float4*)ln_b + (tid - 128));
        else                cp16(smu + B2C * 4 + (tid - 192) * 16, (const float4*)b2 + (tid - 192));
        if (tid < 16)       cp16(smu + B3C * 4 + tid * 16, (const float4*)b3 + tid);
        CP_COMMIT();
    }
    // ---- chunk 1 (W1) : group 1 ---------------------------------------------
    {
        const float4* src = (const float4*)(g_w1 + BUFSZ);
        const uint32_t dst = smu + (BUF + BUFSZ) * 4;
        for (int i = tid; i < BUFSZ / 4; i += THREADS) cp16(dst + i * 16, src + i);
        CP_COMMIT();
    }

    // ---- assemble X (tf32) + ego passthrough --------------------------------
    for (int i = tid; i < M * K1; i += THREADS) {
        const int r = i / K1, c = i - r * K1;
        float v = 0.0f;
        if (r < RVALID) {
            const int bl = r / NEIGH, n = r - bl * NEIGH;
            const float* ob = obs + (size_t)(b0 + bl) * OBS_DIM;
            if (c < EGO)      v = ob[c];
            else if (c < 72)  v = ob[EGO + (c - EGO) * NEIGH + n];
            else if (c == 72) v = (n >= 3) ? 1.0f : 0.0f;
        }
        sm[XO + r * XS + c] = __uint_as_float(tf32r(v));
    }
    for (int i = tid; i < BPB * EGO; i += THREADS) {
        const int bb = i / EGO, f = i - bb * EGO;
        out[(size_t)(b0 + bb) * OUT_DIM + f] = obs[(size_t)(b0 + bb) * OBS_DIM + f];
    }

    float d[2][8][4];
#pragma unroll
    for (int t = 0; t < 2; ++t)
#pragma unroll
        for (int j = 0; j < 8; ++j)
#pragma unroll
            for (int e = 0; e < 4; ++e) d[t][j][e] = 0.0f;

    // ---- GEMM1: chunks 0..2 -------------------------------------------------
    for (int c = 0; c < 3; ++c) {
        CP_WAIT(1);
        __syncthreads();
        gemm_chunk(sm + XO, XS, c * 32, sm + BUF + (c & 1) * BUFSZ, d, rb, cb, lane);
        __syncthreads();
        // prefetch chunk c+2 into this buffer
        const int nc = c + 2;
        const float* gsrc = (nc < 3) ? (g_w1 + nc * BUFSZ) : (g_w2 + (nc - 3) * BUFSZ);
        const uint32_t dst = smu + (BUF + (c & 1) * BUFSZ) * 4;
        for (int i = tid; i < BUFSZ / 4; i += THREADS)
            cp16(dst + i * 16, (const float4*)gsrc + i);
        CP_COMMIT();
    }

    // ---- epilogue 1: +b1, LayerNorm, tanh -> h1 (tf32) ----------------------
    {
        float b1c[16], gc[16], bbc[16];
#pragma unroll
        for (int j = 0; j < 8; ++j)
#pragma unroll
            for (int e = 0; e < 2; ++e) {
                const int col = cb + j * 8 + lr * 2 + e;
                b1c[2 * j + e] = sm[B1C + col];
                gc [2 * j + e] = sm[GC  + col];
                bbc[2 * j + e] = sm[BBC + col];
            }
        float s[2][2], q[2][2];
#pragma unroll
        for (int t = 0; t < 2; ++t)
#pragma unroll
            for (int h = 0; h < 2; ++h) { s[t][h] = 0.0f; q[t][h] = 0.0f; }
#pragma unroll
        for (int t = 0; t < 2; ++t)
#pragma unroll
            for (int j = 0; j < 8; ++j)
#pragma unroll
                for (int e = 0; e < 4; ++e) {
                    const float v = d[t][j][e] + b1c[2 * j + (e & 1)];
                    d[t][j][e] = v;
                    s[t][e >> 1] += v;
                    q[t][e >> 1] = fmaf(v, v, q[t][e >> 1]);
                }
#pragma unroll
        for (int t = 0; t < 2; ++t)
#pragma unroll
            for (int h = 0; h < 2; ++h) {
#pragma unroll
                for (int o = 1; o < 4; o <<= 1) {
                    s[t][h] += __shfl_xor_sync(0xffffffffu, s[t][h], o);
                    q[t][h] += __shfl_xor_sync(0xffffffffu, q[t][h], o);
                }
            }
        if (lr == 0) {
#pragma unroll
            for (int t = 0; t < 2; ++t)
#pragma unroll
                for (int h = 0; h < 2; ++h) {
                    const int r = rb + t * 16 + h * 8 + lq;
                    sm[PSU + wc * 64 + r] = s[t][h];
                    sm[PSQ + wc * 64 + r] = q[t][h];
                }
        }
        __syncthreads();
        float mu[2][2], rs[2][2];
#pragma unroll
        for (int t = 0; t < 2; ++t)
#pragma unroll
            for (int h = 0; h < 2; ++h) {
                const int r = rb + t * 16 + h * 8 + lq;
                const float ts  = sm[PSU + r] + sm[PSU + 64 + r] + sm[PSU + 128 + r] + sm[PSU + 192 + r];
                const float tq  = sm[PSQ + r] + sm[PSQ + 64 + r] + sm[PSQ + 128 + r] + sm[PSQ + 192 + r];
                mu[t][h] = ts * (1.0f / 256.0f);
                const float var = fmaf(tq, 1.0f / 256.0f, -mu[t][h] * mu[t][h]);
                rs[t][h] = rsqrtf(var + 1e-5f);
            }
#pragma unroll
        for (int t = 0; t < 2; ++t)
#pragma unroll
            for (int j = 0; j < 8; ++j)
#pragma unroll
                for (int e = 0; e < 4; ++e) {
                    const int h = e >> 1;
                    const int r = rb + t * 16 + h * 8 + lq;
                    const int col = cb + j * 8 + lr * 2 + (e & 1);
                    const float y = tanhf(fmaf((d[t][j][e] - mu[t][h]) * rs[t][h],
                                               gc[2 * j + (e & 1)], bbc[2 * j + (e & 1)]));
                    sm[H1O + r * H1S + col] = __uint_as_float(tf32r(y));
                    d[t][j][e] = 0.0f;   // re-zero for GEMM2
                }
    }

    // ---- GEMM2: chunks 3..10 ------------------------------------------------
    for (int c = 3; c < NCHUNK; ++c) {
        CP_WAIT(1);
        __syncthreads();
        gemm_chunk(sm + H1O, H1S, (c - 3) * 32, sm + BUF + (c & 1) * BUFSZ, d, rb, cb, lane);
        __syncthreads();
        if (c + 2 < NCHUNK) {
            const float* gsrc = g_w2 + (c - 1) * BUFSZ;
            const uint32_t dst = smu + (BUF + (c & 1) * BUFSZ) * 4;
            for (int i = tid; i < BUFSZ / 4; i += THREADS)
                cp16(dst + i * 16, (const float4*)gsrc + i);
            CP_COMMIT();
        }
    }

    // ---- W3 -> BUF region (now free) ----------------------------------------
    {
        const uint32_t dst = smu + BUF * 4;
        for (int i = tid; i < H * DOUT / 4; i += THREADS)
            cp16(dst + i * 16, (const float4*)W3 + i);
        CP_COMMIT();
    }

    // ---- epilogue 2: +b2, ELU -> stage in h1 region -------------------------
    {
        float b2c[16];
#pragma unroll
        for (int j = 0; j < 8; ++j)
#pragma unroll
            for (int e = 0; e < 2; ++e)
                b2c[2 * j + e] = sm[B2C + cb + j * 8 + lr * 2 + e];
#pragma unroll
        for (int t = 0; t < 2; ++t)
#pragma unroll
            for (int j = 0; j < 8; ++j)
#pragma unroll
                for (int e = 0; e < 4; ++e) {
                    const int h = e >> 1;
                    const int r = rb + t * 16 + h * 8 + lq;
                    const int col = cb + j * 8 + lr * 2 + (e & 1);
                    float v = d[t][j][e] + b2c[2 * j + (e & 1)];
                    v = (v > 0.0f) ? v : expm1f(v);
                    sm[H1O + r * H1S + col] = v;
                }
    }
    __syncthreads();

    // ---- neighbor-sum -> ss[8][256] -----------------------------------------
    {
        const int b = tid >> 5, c0 = (tid & 31) * 8;
        float4 a0 = make_float4(0.f, 0.f, 0.f, 0.f);
        float4 a1 = make_float4(0.f, 0.f, 0.f, 0.f);
        const float* base = sm + H1O + (b * NEIGH) * H1S + c0;
#pragma unroll
        for (int n = 0; n < NEIGH; ++n) {
            const float4 u0 = *(const float4*)(base + n * H1S);
            const float4 u1 = *(const float4*)(base + n * H1S + 4);
            a0.x += u0.x; a0.y += u0.y; a0.z += u0.z; a0.w += u0.w;
            a1.x += u1.x; a1.y += u1.y; a1.z += u1.z; a1.w += u1.w;
        }
        *(float4*)(sm + SSO + b * H + c0)     = a0;
        *(float4*)(sm + SSO + b * H + c0 + 4) = a1;
    }
    CP_WAIT(0);
    __syncthreads();

    // ---- GEMM3 (SIMT): latent = ss @ W3 + b3 --------------------------------
    {
        const int b = tid >> 5, o = tid & 31;
        const float* ssr = sm + SSO + b * H;
        const float* w3  = sm + BUF;
        float a0 = 0.0f, a1 = 0.0f;
#pragma unroll 4
        for (int k = 0; k < H; ++k) {
            const float s = ssr[k];
            a0 = fmaf(s, w3[k * DOUT + o],      a0);
            a1 = fmaf(s, w3[k * DOUT + o + 32], a1);
        }
        float* orow = out + (size_t)(b0 + b) * OUT_DIM + EGO;
        orow[o]      = a0 + sm[B3C + o];
        orow[o + 32] = a1 + sm[B3C + o + 32];
    }
}

extern "C" void kernel_launch(void* const* d_in, const int* in_sizes, int n_in,
                              void* d_out, int out_size)
{
    (void)in_sizes; (void)n_in; (void)out_size;
    const float* obs  = (const float*)d_in[0];
    const float* W1   = (const float*)d_in[1];
    const float* b1   = (const float*)d_in[2];
    const float* ln_g = (const float*)d_in[3];
    const float* ln_b = (const float*)d_in[4];
    const float* W2   = (const float*)d_in[5];
    const float* b2   = (const float*)d_in[6];
    const float* W3   = (const float*)d_in[7];
    const float* b3   = (const float*)d_in[8];
    float* out = (float*)d_out;

    const int prep_elems = (K1 + H) * WS;
    prep_kernel<<<(prep_elems + 255) / 256, 256>>>(W1, W2);

    cudaFuncSetAttribute(enc3_mma_kernel, cudaFuncAttributeMaxDynamicSharedMemorySize, SMEM_BYTES);
    enc3_mma_kernel<<<BATCHES / BPB, THREADS, SMEM_BYTES>>>(
        obs, b1, ln_g, ln_b, b2, W3, b3, out);
}

// round 6
// speedup vs baseline: 2.0309x; 1.0548x over previous
#include <cuda_runtime.h>
#include <math.h>
#include <stdint.h>

// ===========================================================================
// EncoderAttention3 via mma.sync tf32 (m16n8k8), register accumulators.
// R5 (resubmit after infra failure): 2 CTAs/SM (smem 112 KB,
// launch_bounds(256,2)), 16-row weight chunks, X aliased into h1 region,
// W3 via LDG, cp.async tail-wait fix.
// ===========================================================================

namespace {
constexpr int OBS_DIM = 216, EGO = 48, NEIGH = 7, H = 256, DOUT = 64, OUT_DIM = 112;
constexpr int BATCHES = 16384;
constexpr int BPB     = 8;
constexpr int RVALID  = BPB * NEIGH;   // 56
constexpr int M       = 64;
constexpr int K1      = 96;            // padded 73 -> 96
constexpr int THREADS = 256;
constexpr int CH      = 16;            // weight chunk rows
constexpr int NC1     = K1 / CH;       // 6
constexpr int NC2     = H / CH;        // 16
constexpr int NCHUNK  = NC1 + NC2;     // 22
constexpr int WS      = 264;           // weight chunk row stride
constexpr int XS      = 100;           // X row stride
constexpr int H1S     = 260;           // h1 row stride
constexpr int BUFSZ   = CH * WS;       // 4224

// smem layout (float offsets)
constexpr int B1C = 0;                 // 256
constexpr int GC  = 256;               // 256
constexpr int BBC = 512;               // 256
constexpr int B2C = 768;               // 256
constexpr int B3C = 1024;              // 64
constexpr int PSU = 1088;              // [4][64]
constexpr int PSQ = 1344;              // [4][64]
constexpr int SSO = 1600;              // ss [8][256]
constexpr int H1O = 3648;              // h1 [64][260]  (X aliases this region)
constexpr int XO  = H1O;               // X  [64][100]
constexpr int BUF = H1O + 64 * H1S;    // 20288: 2 x [16][264] chunk buffers
constexpr int SMEM_FLOATS = BUF + 2 * BUFSZ;   // 28736
constexpr int SMEM_BYTES  = SMEM_FLOATS * 4;   // 114944 (2 CTAs/SM)
}  // namespace

__device__ float g_w1[K1 * WS];        // tf32-rounded, padded [96][264]
__device__ float g_w2[H * WS];         // tf32-rounded, padded [256][264]

// ---------------------------------------------------------------------------
__device__ __forceinline__ uint32_t tf32r(float f) {
    uint32_t u;
    asm("cvt.rna.tf32.f32 %0, %1;" : "=r"(u) : "f"(f));
    return u;
}
__device__ __forceinline__ void cp16(uint32_t dst, const void* src) {
    asm volatile("cp.async.cg.shared.global [%0], [%1], 16;" :: "r"(dst), "l"(src));
}
#define CP_COMMIT() asm volatile("cp.async.commit_group;" ::: "memory")
#define CP_WAIT(n)  asm volatile("cp.async.wait_group %0;" :: "n"(n) : "memory")

__device__ __forceinline__ void mma8(float d[4], const uint32_t a[4],
                                     uint32_t b0, uint32_t b1) {
    asm volatile("mma.sync.aligned.m16n8k8.row.col.f32.tf32.tf32.f32 "
                 "{%0,%1,%2,%3},{%4,%5,%6,%7},{%8,%9},{%0,%1,%2,%3};"
                 : "+f"(d[0]), "+f"(d[1]), "+f"(d[2]), "+f"(d[3])
                 : "r"(a[0]), "r"(a[1]), "r"(a[2]), "r"(a[3]), "r"(b0), "r"(b1));
}

// one 16-row K-chunk: A[64 x *] (smem, stride as), B chunk buf [16][WS]
__device__ __forceinline__ void gemm_chunk16(const float* __restrict__ A, int as, int k0,
                                             const float* __restrict__ B,
                                             float d[2][8][4], int rb, int cb, int lane) {
    const int lq = lane >> 2, lr = lane & 3;
#pragma unroll
    for (int ks = 0; ks < 2; ++ks) {
        const int kk = ks * 8;
        uint32_t a[2][4];
#pragma unroll
        for (int t = 0; t < 2; ++t) {
            const float* ap = A + (rb + t * 16 + lq) * as + k0 + kk + lr;
            a[t][0] = __float_as_uint(ap[0]);
            a[t][1] = __float_as_uint(ap[8 * as]);
            a[t][2] = __float_as_uint(ap[4]);
            a[t][3] = __float_as_uint(ap[8 * as + 4]);
        }
#pragma unroll
        for (int j = 0; j < 8; ++j) {
            const float* bp = B + (kk + lr) * WS + cb + j * 8 + lq;
            const uint32_t b0 = __float_as_uint(bp[0]);
            const uint32_t b1 = __float_as_uint(bp[4 * WS]);
            mma8(d[0][j], a[0], b0, b1);
            mma8(d[1][j], a[1], b0, b1);
        }
    }
}

// ---------------------------------------------------------------------------
__global__ void prep_kernel(const float* __restrict__ W1, const float* __restrict__ W2) {
    const int idx = blockIdx.x * blockDim.x + threadIdx.x;
    if (idx < K1 * WS) {
        const int k = idx / WS, n = idx - k * WS;
        const float v = (k < 73 && n < H) ? W1[k * H + n] : 0.0f;
        g_w1[idx] = __uint_as_float(tf32r(v));
    } else if (idx < (K1 + H) * WS) {
        const int i2 = idx - K1 * WS;
        const int k = i2 / WS, n = i2 - k * WS;
        const float v = (n < H) ? W2[k * H + n] : 0.0f;
        g_w2[i2] = __uint_as_float(tf32r(v));
    }
}

// ---------------------------------------------------------------------------
__global__ void __launch_bounds__(THREADS, 2)
enc3_mma_kernel(const float* __restrict__ obs,
                const float* __restrict__ b1, const float* __restrict__ ln_g,
                const float* __restrict__ ln_b, const float* __restrict__ b2,
                const float* __restrict__ W3, const float* __restrict__ b3,
                float* __restrict__ out)
{
    extern __shared__ float sm[];
    const int tid  = threadIdx.x;
    const int wid  = tid >> 5;
    const int lane = tid & 31;
    const int lq   = lane >> 2, lr = lane & 3;
    const int rb   = (wid >> 2) * 32;    // row group base (0/32)
    const int cb   = (wid & 3) * 64;     // col group base
    const int b0   = blockIdx.x * BPB;
    const uint32_t smu = (uint32_t)__cvta_generic_to_shared(sm);

    // ---- group0: chunk 0 + const vectors ------------------------------------
    {
        const float4* src = (const float4*)g_w1;
        const uint32_t dst = smu + BUF * 4;
        for (int i = tid; i < BUFSZ / 4; i += THREADS) cp16(dst + i * 16, src + i);
        if (tid < 64)       cp16(smu + B1C * 4 + tid * 16, (const float4*)b1 + tid);
        else if (tid < 128) cp16(smu + GC  * 4 + (tid - 64) * 16, (const float4*)ln_g + (tid - 64));
        else if (tid < 192) cp16(smu + BBC * 4 + (tid - 128) * 16, (const float4*)ln_b + (tid - 128));
        else                cp16(smu + B2C * 4 + (tid - 192) * 16, (const float4*)b2 + (tid - 192));
        if (tid < 16)       cp16(smu + B3C * 4 + tid * 16, (const float4*)b3 + tid);
        CP_COMMIT();
    }
    // ---- group1: chunk 1 ----------------------------------------------------
    {
        const float4* src = (const float4*)(g_w1 + BUFSZ);
        const uint32_t dst = smu + (BUF + BUFSZ) * 4;
        for (int i = tid; i < BUFSZ / 4; i += THREADS) cp16(dst + i * 16, src + i);
        CP_COMMIT();
    }

    // ---- assemble X (tf32) + ego passthrough --------------------------------
    for (int i = tid; i < M * K1; i += THREADS) {
        const int r = i / K1, c = i - r * K1;
        float v = 0.0f;
        if (r < RVALID) {
            const int bl = r / NEIGH, n = r - bl * NEIGH;
            const float* ob = obs + (size_t)(b0 + bl) * OBS_DIM;
            if (c < EGO)      v = ob[c];
            else if (c < 72)  v = ob[EGO + (c - EGO) * NEIGH + n];
            else if (c == 72) v = (n >= 3) ? 1.0f : 0.0f;
        }
        sm[XO + r * XS + c] = __uint_as_float(tf32r(v));
    }
    for (int i = tid; i < BPB * EGO; i += THREADS) {
        const int bb = i / EGO, f = i - bb * EGO;
        out[(size_t)(b0 + bb) * OUT_DIM + f] = obs[(size_t)(b0 + bb) * OBS_DIM + f];
    }

    float d[2][8][4];
#pragma unroll
    for (int t = 0; t < 2; ++t)
#pragma unroll
        for (int j = 0; j < 8; ++j)
#pragma unroll
            for (int e = 0; e < 4; ++e) d[t][j][e] = 0.0f;

    // ---- GEMM1: chunks 0..5 -------------------------------------------------
    for (int c = 0; c < NC1; ++c) {
        CP_WAIT(1);
        __syncthreads();
        gemm_chunk16(sm + XO, XS, c * CH, sm + BUF + (c & 1) * BUFSZ, d, rb, cb, lane);
        __syncthreads();
        const int nc = c + 2;   // always < NCHUNK here
        const float* gsrc = (nc < NC1) ? (g_w1 + nc * BUFSZ) : (g_w2 + (nc - NC1) * BUFSZ);
        const uint32_t dst = smu + (BUF + (c & 1) * BUFSZ) * 4;
        for (int i = tid; i < BUFSZ / 4; i += THREADS)
            cp16(dst + i * 16, (const float4*)gsrc + i);
        CP_COMMIT();
    }

    // ---- epilogue 1: +b1, LayerNorm, tanh -> h1 (tf32, overwrites X region) --
    {
        float s[2][2] = {{0.f, 0.f}, {0.f, 0.f}};
        float q[2][2] = {{0.f, 0.f}, {0.f, 0.f}};
#pragma unroll
        for (int t = 0; t < 2; ++t)
#pragma unroll
            for (int j = 0; j < 8; ++j)
#pragma unroll
                for (int e = 0; e < 4; ++e) {
                    const float v = d[t][j][e] + sm[B1C + cb + j * 8 + lr * 2 + (e & 1)];
                    d[t][j][e] = v;
                    s[t][e >> 1] += v;
                    q[t][e >> 1] = fmaf(v, v, q[t][e >> 1]);
                }
#pragma unroll
        for (int t = 0; t < 2; ++t)
#pragma unroll
            for (int h = 0; h < 2; ++h)
#pragma unroll
                for (int o = 1; o < 4; o <<= 1) {
                    s[t][h] += __shfl_xor_sync(0xffffffffu, s[t][h], o);
                    q[t][h] += __shfl_xor_sync(0xffffffffu, q[t][h], o);
                }
        if (lr == 0) {
#pragma unroll
            for (int t = 0; t < 2; ++t)
#pragma unroll
                for (int h = 0; h < 2; ++h) {
                    const int r = rb + t * 16 + h * 8 + lq;
                    sm[PSU + (wid & 3) * 64 + r] = s[t][h];
                    sm[PSQ + (wid & 3) * 64 + r] = q[t][h];
                }
        }
        __syncthreads();
        float mu[2][2], rs[2][2];
#pragma unroll
        for (int t = 0; t < 2; ++t)
#pragma unroll
            for (int h = 0; h < 2; ++h) {
                const int r = rb + t * 16 + h * 8 + lq;
                const float ts = sm[PSU + r] + sm[PSU + 64 + r] + sm[PSU + 128 + r] + sm[PSU + 192 + r];
                const float tq = sm[PSQ + r] + sm[PSQ + 64 + r] + sm[PSQ + 128 + r] + sm[PSQ + 192 + r];
                mu[t][h] = ts * (1.0f / 256.0f);
                const float var = fmaf(tq, 1.0f / 256.0f, -mu[t][h] * mu[t][h]);
                rs[t][h] = rsqrtf(var + 1e-5f);
            }
        __syncthreads();   // all warps have read X / PSU before h1 overwrites region
#pragma unroll
        for (int t = 0; t < 2; ++t)
#pragma unroll
            for (int j = 0; j < 8; ++j)
#pragma unroll
                for (int e = 0; e < 4; ++e) {
                    const int h = e >> 1;
                    const int r = rb + t * 16 + h * 8 + lq;
                    const int col = cb + j * 8 + lr * 2 + (e & 1);
                    const float y = tanhf(fmaf((d[t][j][e] - mu[t][h]) * rs[t][h],
                                               sm[GC + col], sm[BBC + col]));
                    sm[H1O + r * H1S + col] = __uint_as_float(tf32r(y));
                    d[t][j][e] = 0.0f;
                }
    }

    // ---- GEMM2: chunks 6..21 ------------------------------------------------
    for (int c = NC1; c < NCHUNK; ++c) {
        if (c == NCHUNK - 1) { CP_WAIT(0); } else { CP_WAIT(1); }
        __syncthreads();
        gemm_chunk16(sm + H1O, H1S, (c - NC1) * CH, sm + BUF + (c & 1) * BUFSZ, d, rb, cb, lane);
        __syncthreads();
        if (c + 2 < NCHUNK) {
            const float* gsrc = g_w2 + (c + 2 - NC1) * BUFSZ;
            const uint32_t dst = smu + (BUF + (c & 1) * BUFSZ) * 4;
            for (int i = tid; i < BUFSZ / 4; i += THREADS)
                cp16(dst + i * 16, (const float4*)gsrc + i);
            CP_COMMIT();
        }
    }

    // ---- epilogue 2: +b2, ELU -> h2 (overwrites h1 region) ------------------
#pragma unroll
    for (int t = 0; t < 2; ++t)
#pragma unroll
        for (int j = 0; j < 8; ++j)
#pragma unroll
            for (int e = 0; e < 4; ++e) {
                const int h = e >> 1;
                const int r = rb + t * 16 + h * 8 + lq;
                const int col = cb + j * 8 + lr * 2 + (e & 1);
                float v = d[t][j][e] + sm[B2C + col];
                v = (v > 0.0f) ? v : expm1f(v);
                sm[H1O + r * H1S + col] = v;
            }
    __syncthreads();

    // ---- neighbor-sum -> ss[8][256] -----------------------------------------
    {
        const int b = tid >> 5, c0 = (tid & 31) * 8;
        float4 a0 = make_float4(0.f, 0.f, 0.f, 0.f);
        float4 a1 = make_float4(0.f, 0.f, 0.f, 0.f);
        const float* base = sm + H1O + (b * NEIGH) * H1S + c0;
#pragma unroll
        for (int n = 0; n < NEIGH; ++n) {
            const float4 u0 = *(const float4*)(base + n * H1S);
            const float4 u1 = *(const float4*)(base + n * H1S + 4);
            a0.x += u0.x; a0.y += u0.y; a0.z += u0.z; a0.w += u0.w;
            a1.x += u1.x; a1.y += u1.y; a1.z += u1.z; a1.w += u1.w;
        }
        *(float4*)(sm + SSO + b * H + c0)     = a0;
        *(float4*)(sm + SSO + b * H + c0 + 4) = a1;
    }
    __syncthreads();

    // ---- GEMM3 (SIMT, W3 via LDG/L1): latent = ss @ W3 + b3 -----------------
    {
        const int b = tid >> 5, o = tid & 31;
        const float* ssr = sm + SSO + b * H;
        float a0 = 0.0f, a1 = 0.0f;
#pragma unroll 4
        for (int k = 0; k < H; ++k) {
            const float s = ssr[k];
            a0 = fmaf(s, __ldg(W3 + k * DOUT + o),      a0);
            a1 = fmaf(s, __ldg(W3 + k * DOUT + o + 32), a1);
        }
        float* orow = out + (size_t)(b0 + b) * OUT_DIM + EGO;
        orow[o]      = a0 + sm[B3C + o];
        orow[o + 32] = a1 + sm[B3C + o + 32];
    }
}

extern "C" void kernel_launch(void* const* d_in, const int* in_sizes, int n_in,
                              void* d_out, int out_size)
{
    (void)in_sizes; (void)n_in; (void)out_size;
    const float* obs  = (const float*)d_in[0];
    const float* W1   = (const float*)d_in[1];
    const float* b1   = (const float*)d_in[2];
    const float* ln_g = (const float*)d_in[3];
    const float* ln_b = (const float*)d_in[4];
    const float* W2   = (const float*)d_in[5];
    const float* b2   = (const float*)d_in[6];
    const float* W3   = (const float*)d_in[7];
    const float* b3   = (const float*)d_in[8];
    float* out = (float*)d_out;

    const int prep_elems = (K1 + H) * WS;
    prep_kernel<<<(prep_elems + 255) / 256, 256>>>(W1, W2);

    cudaFuncSetAttribute(enc3_mma_kernel, cudaFuncAttributeMaxDynamicSharedMemorySize, SMEM_BYTES);
    enc3_mma_kernel<<<BATCHES / BPB, THREADS, SMEM_BYTES>>>(
        obs, b1, ln_g, ln_b, b2, W3, b3, out);
}